// round 9
// baseline (speedup 1.0000x reference)
#include <cuda_runtime.h>

// Problem constants (fixed by setup_inputs)
#define B_    4
#define C_    256
#define H_    256
#define W_    512
#define FS    14
#define NP    (FS*FS)        // 196
#define NROI  400            // B * MAXLOAD
#define HW    (H_*W_)        // 131072
#define HB    (B_*H_)        // 1024 stacked rows
#define CH    8              // channels per slab (one warp stages one channel)
#define NSLAB (C_/CH)        // 32
#define NY    1024           // y-buckets (global stacked row)
#define CAP   1408           // max (n,i) entries per bucket (hard upper bound 1400)
#define SPANW 130            // max float4 words per staged row (512/4 + pad)
#define THREADS 256

static const long OUT_MAIN = (long)NROI * C_ * NP;   // 20,070,400

// Bucket scratch (device globals: allocation-free)
__device__ int            g_cnt [NY];
__device__ int            g_minx[NY];
__device__ int            g_maxx[NY];
__device__ unsigned short g_ent [NY][CAP];

// ---- coordinate pipeline, exactly as reference ----
__device__ __forceinline__ float px_of(float j, float scalex, float biasx)
{
    float gridx = (j * (1.0f / 13.0f) * scalex + biasx) * 0.25f;
    float gx = (gridx * (1.0f / (W_ - 1)) - 0.5f) * 2.0f;
    float px = ((gx + 1.0f) * (float)W_ - 1.0f) * 0.5f;
    return fminf(fmaxf(px, 0.0f), (float)(W_ - 1));
}
__device__ __forceinline__ float py_of(float i, float scaley, float biasy)
{
    float gridy = (i * (1.0f / 13.0f) * scaley + biasy) * 0.25f;
    float gy = (gridy * (1.0f / (HB - 1)) - 0.5f) * 2.0f;
    float py = ((gy + 1.0f) * (float)HB - 1.0f) * 0.5f;
    return fminf(fmaxf(py, 0.0f), (float)(HB - 1));
}

// ---- kernel 1: reset buckets + write val_bind tail ----
__global__ void reset_kernel(float* __restrict__ out, long out_size)
{
    int t = blockIdx.x * blockDim.x + threadIdx.x;
    if (t < NY) {
        g_cnt[t]  = 0;
        g_minx[t] = 0x7FFFFFFF;
        g_maxx[t] = -1;
    }
    long tail = out_size - OUT_MAIN;
    for (long k = t; k < tail; k += (long)gridDim.x * blockDim.x)
        out[OUT_MAIN + k] = (float)((int)(k / 100));
}

// ---- kernel 2: bucket each (roi n, grid row i) by its y0 row ----
__global__ void build_kernel(const float* __restrict__ rois)
{
    int t = blockIdx.x * blockDim.x + threadIdx.x;
    if (t >= NROI * FS) return;
    int n = t / FS;
    int i = t - n * FS;
    int b = n / 100;

    const float4 r = reinterpret_cast<const float4*>(rois)[n];
    float py = py_of((float)i, r.w - r.y, r.y + (float)b * 1024.0f);
    int   y0 = (int)floorf(py);

    float pxs = px_of(0.0f,  r.z - r.x, r.x);
    float pxe = px_of(13.0f, r.z - r.x, r.x);
    int xs = (int)floorf(pxs);
    int xe = min((int)floorf(pxe) + 1, W_ - 1);

    int slot = atomicAdd(&g_cnt[y0], 1);
    g_ent[y0][slot] = (unsigned short)(n * 16 + i);
    atomicMin(&g_minx[y0], xs);
    atomicMax(&g_maxx[y0], xe);
}

// ---- kernel 3: one CTA per (channel slab, y bucket) ----
__global__ __launch_bounds__(THREADS)
void pooler_bucket_kernel(const float* __restrict__ feat,
                          const float* __restrict__ rois,
                          float*       __restrict__ out)
{
    __shared__ __align__(16) float tile[CH][2][SPANW * 4];

    const int y    = blockIdx.x & (NY - 1);
    const int slab = blockIdx.x >> 10;
    const int cnt  = g_cnt[y];
    if (cnt == 0) return;

    const int c0    = slab * CH;
    const int minx4 = g_minx[y] & ~3;
    const int span4 = ((g_maxx[y] - minx4) >> 2) + 1;   // <=129 float4 words
    const int y2    = min(y + 1, HB - 1);
    const int tid   = threadIdx.x;

    // stage rows y and y2 for CH channels, dense coalesced float4
    {
        int w    = tid >> 5;            // warp = channel lane
        int lane = tid & 31;
        int ch   = c0 + w;
        const float4* f4 = reinterpret_cast<const float4*>(feat);
        int b0 = ((((y  >> 8) * C_ + ch) * HW + (y  & 255) * W_ + minx4) >> 2);
        int b1 = ((((y2 >> 8) * C_ + ch) * HW + (y2 & 255) * W_ + minx4) >> 2);
        float4* t0 = reinterpret_cast<float4*>(tile[w][0]);
        float4* t1 = reinterpret_cast<float4*>(tile[w][1]);
        for (int wd = lane; wd < span4; wd += 32) {
            t0[wd] = __ldg(f4 + b0 + wd);
            t1[wd] = __ldg(f4 + b1 + wd);
        }
    }
    __syncthreads();

    // serve entries: 2 entries per pass, 112 threads each (8 ch x 14 j)
    const int le  = tid / 112;          // 0,1 (tid<224 active)
    const int idx = tid - le * 112;
    const int ch  = idx / FS;
    const int j   = idx - ch * FS;

    for (int base = 0; base < cnt; base += 2) {
        if (tid < 224 && base + le < cnt) {
            int e = g_ent[y][base + le];
            int n = e >> 4;
            int i = e & 15;
            int b = n / 100;

            const float4 r = reinterpret_cast<const float4*>(rois)[n];
            float py = py_of((float)i, r.w - r.y, r.y + (float)b * 1024.0f);
            float wy = py - floorf(py);

            float px = px_of((float)j, r.z - r.x, r.x);
            float x0f = floorf(px);
            float wx  = px - x0f;
            int x0 = (int)x0f;
            int x1 = min(x0 + 1, W_ - 1);
            int o0 = x0 - minx4;
            int o1 = x1 - minx4;

            float f00 = tile[ch][0][o0];
            float f01 = tile[ch][0][o1];
            float f10 = tile[ch][1][o0];
            float f11 = tile[ch][1][o1];

            float omwx = 1.0f - wx;
            float omwy = 1.0f - wy;
            float v = (f00 * omwx + f01 * wx) * omwy
                    + (f10 * omwx + f11 * wx) * wy;

            out[(n * C_ + c0 + ch) * NP + i * FS + j] = v;
        }
    }
}

extern "C" void kernel_launch(void* const* d_in, const int* in_sizes, int n_in,
                              void* d_out, int out_size)
{
    const float* feat = (const float*)d_in[0];
    const float* rois = (const float*)d_in[1];
    float* out = (float*)d_out;

    reset_kernel<<<4, 256>>>(out, (long)out_size);
    build_kernel<<<(NROI * FS + 255) / 256, 256>>>(rois);
    pooler_bucket_kernel<<<NSLAB * NY, THREADS>>>(feat, rois, out);
}

// round 10
// speedup vs baseline: 1.8634x; 1.8634x over previous
#include <cuda_runtime.h>

// Problem constants (fixed by setup_inputs)
#define B_    4
#define C_    256
#define H_    256
#define W_    512
#define FS    14
#define NP    (FS*FS)        // 196
#define NROI  400            // B * MAXLOAD
#define HW    (H_*W_)        // 131072
#define HB    (B_*H_)        // 1024 stacked rows
#define KCH   4              // channels per thread
#define NCQ   (C_/KCH)       // 64 channel groups

#define THREADS 256

static const long OUT_MAIN   = (long)NROI * C_ * NP;      // 20,070,400
#define MAIN_THREADS (NROI * NCQ * NP)                    // 5,017,600
#define MAIN_BLOCKS  (MAIN_THREADS / THREADS)             // 19,600 (exact)

__global__ __launch_bounds__(THREADS)
void pooler_p2_kernel(const float* __restrict__ feat,
                      const float* __restrict__ rois,
                      float*       __restrict__ out,
                      long out_size)
{
    int t = blockIdx.x * THREADS + threadIdx.x;

    // Tail: val_bind = repeat(arange(B), MAXLOAD) appended after main output.
    if (t >= MAIN_THREADS) {
        long k   = (long)(t - MAIN_THREADS);
        long idx = OUT_MAIN + k;
        if (idx < out_size) out[idx] = (float)((int)(k / 100));
        return;
    }

    // Decode: p fastest (warp coalescing), n middle, cq SLOWEST
    // (channel-slab ordering: a wave covers all ROIs in a narrow slab -> L2 reuse)
    int p  = t % NP;
    int q  = t / NP;
    int n  = q % NROI;
    int cq = q / NROI;
    int c  = cq * KCH;
    int i  = p / FS;
    int j  = p - i * FS;
    int b  = n / 100;                         // roi's batch

    const float4 r = reinterpret_cast<const float4*>(rois)[n];
    const float inv13 = 1.0f / 13.0f;

    float scalex = r.z - r.x;
    float scaley = r.w - r.y;
    float biasy  = r.y + (float)b * 1024.0f;  // image_height

    float gridx = ((float)j * inv13 * scalex + r.x)  * 0.25f;  // /shrink_scale
    float gridy = ((float)i * inv13 * scaley + biasy) * 0.25f;

    // normalized-grid round trip, exactly as reference
    float gx = (gridx * (1.0f / (W_ - 1)) - 0.5f) * 2.0f;
    float gy = (gridy * (1.0f / (HB - 1)) - 0.5f) * 2.0f;
    float px = ((gx + 1.0f) * (float)W_ - 1.0f) * 0.5f;
    float py = ((gy + 1.0f) * (float)HB - 1.0f) * 0.5f;
    px = fminf(fmaxf(px, 0.0f), (float)(W_ - 1));
    py = fminf(fmaxf(py, 0.0f), (float)(HB - 1));

    float x0f = floorf(px);
    float y0f = floorf(py);
    float wx  = px - x0f;
    float wy  = py - y0f;
    int x0 = (int)x0f;
    int y0 = (int)y0f;
    int x1 = min(x0 + 1, W_ - 1);
    int y1 = min(y0 + 1, HB - 1);

    // feats view (C, B*H, W); element indices fit in int32 (max ~134M)
    int a0 = ((y0 >> 8) * C_ + c) * HW + (y0 & 255) * W_;
    int a1 = ((y1 >> 8) * C_ + c) * HW + (y1 & 255) * W_;

    // Aligned float2 covers (x0, x0+1) when x0 is even (50% of lanes).
    // Odd lanes get f00 from .y and fetch f01 with a predicated scalar load.
    // Same L1 lines as a single LDG.32 -> ~1.8x wavefronts per corner pair
    // instead of 2x for two scalar loads.
    int  xb  = x0 & ~1;                // 8B-aligned element base
    bool odd = (x0 & 1) != 0;

    const float2* f2 = reinterpret_cast<const float2*>(feat);
    float2 q0[KCH], q1[KCH];
#pragma unroll
    for (int k = 0; k < KCH; k++)
        q0[k] = __ldg(f2 + ((a0 + k * HW + xb) >> 1));
#pragma unroll
    for (int k = 0; k < KCH; k++)
        q1[k] = __ldg(f2 + ((a1 + k * HW + xb) >> 1));

    float e0[KCH], e1[KCH];
#pragma unroll
    for (int k = 0; k < KCH; k++)
        e0[k] = odd ? __ldg(feat + a0 + k * HW + x1) : 0.0f;
#pragma unroll
    for (int k = 0; k < KCH; k++)
        e1[k] = odd ? __ldg(feat + a1 + k * HW + x1) : 0.0f;

    float omwx = 1.0f - wx;
    float omwy = 1.0f - wy;
    long ob = ((long)(n * C_ + c)) * NP + p;
#pragma unroll
    for (int k = 0; k < KCH; k++) {
        float f00 = odd ? q0[k].y : q0[k].x;
        float f10 = odd ? q1[k].y : q1[k].x;
        float f01 = odd ? e0[k]   : q0[k].y;
        float f11 = odd ? e1[k]   : q1[k].y;
        float v = (f00 * omwx + f01 * wx) * omwy
                + (f10 * omwx + f11 * wx) * wy;
        // streaming store: output is never re-read; keep L2 for features
        __stcs(&out[ob + (long)k * NP], v);
    }
}

extern "C" void kernel_launch(void* const* d_in, const int* in_sizes, int n_in,
                              void* d_out, int out_size)
{
    const float* feat = (const float*)d_in[0];
    const float* rois = (const float*)d_in[1];
    float* out = (float*)d_out;

    long tail = (long)out_size - OUT_MAIN;
    int tail_blocks = tail > 0 ? (int)((tail + THREADS - 1) / THREADS) : 0;

    pooler_p2_kernel<<<MAIN_BLOCKS + tail_blocks, THREADS>>>(
        feat, rois, out, (long)out_size);
}

// round 11
// speedup vs baseline: 1.9669x; 1.0556x over previous
#include <cuda_runtime.h>

// Problem constants (fixed by setup_inputs)
#define B_    4
#define C_    256
#define H_    256
#define W_    512
#define FS    14
#define NP    (FS*FS)        // 196
#define NROI  400            // B * MAXLOAD
#define HW    (H_*W_)        // 131072
#define HB    (B_*H_)        // 1024 stacked rows
#define KCH   4              // channels per thread
#define NCQ   (C_/KCH)       // 64 channel groups

#define THREADS 256

static const long OUT_MAIN   = (long)NROI * C_ * NP;      // 20,070,400
#define MAIN_THREADS (NROI * NCQ * NP)                    // 5,017,600
#define MAIN_BLOCKS  (MAIN_THREADS / THREADS)             // 19,600 (exact)

__global__ __launch_bounds__(THREADS)
void pooler_cslab_stcs_kernel(const float* __restrict__ feat,
                              const float* __restrict__ rois,
                              float*       __restrict__ out,
                              long out_size)
{
    int t = blockIdx.x * THREADS + threadIdx.x;

    // Tail: val_bind = repeat(arange(B), MAXLOAD) appended after main output.
    if (t >= MAIN_THREADS) {
        long k   = (long)(t - MAIN_THREADS);
        long idx = OUT_MAIN + k;
        if (idx < out_size) out[idx] = (float)((int)(k / 100));
        return;
    }

    // Decode: p fastest (warp coalescing), n middle, cq SLOWEST.
    // A concurrent wave covers ALL ROIs within a narrow channel slab ->
    // cross-ROI overlaps hit in L2 instead of re-missing to DRAM.
    int p  = t % NP;
    int q  = t / NP;
    int n  = q % NROI;
    int cq = q / NROI;
    int c  = cq * KCH;
    int i  = p / FS;
    int j  = p - i * FS;
    int b  = n / 100;                         // roi's batch

    const float4 r = reinterpret_cast<const float4*>(rois)[n];
    const float inv13 = 1.0f / 13.0f;

    float scalex = r.z - r.x;
    float scaley = r.w - r.y;
    float biasy  = r.y + (float)b * 1024.0f;  // image_height

    float gridx = ((float)j * inv13 * scalex + r.x)  * 0.25f;  // /shrink_scale
    float gridy = ((float)i * inv13 * scaley + biasy) * 0.25f;

    // normalized-grid round trip, exactly as reference
    float gx = (gridx * (1.0f / (W_ - 1)) - 0.5f) * 2.0f;
    float gy = (gridy * (1.0f / (HB - 1)) - 0.5f) * 2.0f;
    float px = ((gx + 1.0f) * (float)W_ - 1.0f) * 0.5f;
    float py = ((gy + 1.0f) * (float)HB - 1.0f) * 0.5f;
    px = fminf(fmaxf(px, 0.0f), (float)(W_ - 1));
    py = fminf(fmaxf(py, 0.0f), (float)(HB - 1));

    float x0f = floorf(px);
    float y0f = floorf(py);
    float wx  = px - x0f;
    float wy  = py - y0f;
    int x0 = (int)x0f;
    int y0 = (int)y0f;
    int x1 = min(x0 + 1, W_ - 1);
    int y1 = min(y0 + 1, HB - 1);

    // feats view (C, B*H, W); element indices fit in int32 (max ~134M)
    int a0 = ((y0 >> 8) * C_ + c) * HW + (y0 & 255) * W_;
    int a1 = ((y1 >> 8) * C_ + c) * HW + (y1 & 255) * W_;

    // Front-batched independent loads (16 LDG.32)
    float f00[KCH], f01[KCH], f10[KCH], f11[KCH];
#pragma unroll
    for (int k = 0; k < KCH; k++) {
        int o = k * HW;
        f00[k] = __ldg(feat + a0 + o + x0);
        f01[k] = __ldg(feat + a0 + o + x1);
        f10[k] = __ldg(feat + a1 + o + x0);
        f11[k] = __ldg(feat + a1 + o + x1);
    }

    float omwx = 1.0f - wx;
    float omwy = 1.0f - wy;
    long ob = ((long)(n * C_ + c)) * NP + p;
#pragma unroll
    for (int k = 0; k < KCH; k++) {
        float v = (f00[k] * omwx + f01[k] * wx) * omwy
                + (f10[k] * omwx + f11[k] * wx) * wy;
        // Streaming store: output is write-once, never re-read.
        // Evict-first keeps L2 capacity for cross-ROI feature reuse.
        __stcs(&out[ob + (long)k * NP], v);
    }
}

extern "C" void kernel_launch(void* const* d_in, const int* in_sizes, int n_in,
                              void* d_out, int out_size)
{
    const float* feat = (const float*)d_in[0];
    const float* rois = (const float*)d_in[1];
    float* out = (float*)d_out;

    long tail = (long)out_size - OUT_MAIN;
    int tail_blocks = tail > 0 ? (int)((tail + THREADS - 1) / THREADS) : 0;

    pooler_cslab_stcs_kernel<<<MAIN_BLOCKS + tail_blocks, THREADS>>>(
        feat, rois, out, (long)out_size);
}